// round 1
// baseline (speedup 1.0000x reference)
#include <cuda_runtime.h>
#include <math.h>

#define T 2048
#define H 1024
#define F 4096
#define E 8
#define NM 4
#define G 8
#define HG (H*G)      /* 8192  */
#define F2 (F/2)      /* 2048  */
#define FG2 (F2*G)    /* 16384 */

// ---------------- scratch (device globals; no allocation allowed) -------------
__device__ float g_b1[(size_t)T * HG];               // 64 MB  rswaf(hidden)
__device__ float g_mid[(size_t)NM * T * F];          // 128 MB per-expert mid (gelu(fc1) or k1)
__device__ float g_b2[(size_t)NM * T * FG2];         // 512 MB per-expert rswaf(k1)
__device__ float g_outslot[2][(size_t)T * H];        // 16 MB  per-(token,slot) weighted outputs
__device__ int   g_tok[E][T];
__device__ float g_wgt[E][T];
__device__ int   g_slot[E][T];
__device__ int   g_cnt[E];

// ---------------- small kernels ------------------------------------------------
__global__ void zero_cnt_kernel() {
    if (threadIdx.x < E) g_cnt[threadIdx.x] = 0;
}

// One block per token; 8 warps = 8 experts. Exact top-2 renormalized softmax.
__global__ void router_kernel(const float* __restrict__ hs, const float* __restrict__ gw) {
    int t = blockIdx.x;
    int warp = threadIdx.x >> 5, lane = threadIdx.x & 31;
    const float* x = hs + (size_t)t * H;
    const float* g = gw + (size_t)warp * H;
    float s = 0.f;
    for (int k = lane; k < H; k += 32) s += x[k] * g[k];
    #pragma unroll
    for (int o = 16; o; o >>= 1) s += __shfl_xor_sync(0xFFFFFFFFu, s, o);
    __shared__ float logits[E];
    if (lane == 0) logits[warp] = s;
    __syncthreads();
    if (threadIdx.x == 0) {
        float l1 = -1e30f, l2 = -1e30f; int e1 = 0, e2 = 0;
        #pragma unroll
        for (int e = 0; e < E; e++) {
            float v = logits[e];
            if (v > l1) { l2 = l1; e2 = e1; l1 = v; e1 = e; }
            else if (v > l2) { l2 = v; e2 = e; }
        }
        float r  = expf(l2 - l1);          // <= 1
        float w1 = 1.0f / (1.0f + r);
        float w2 = r * w1;
        int p1 = atomicAdd(&g_cnt[e1], 1);
        g_tok[e1][p1] = t; g_wgt[e1][p1] = w1; g_slot[e1][p1] = 0;
        int p2 = atomicAdd(&g_cnt[e2], 1);
        g_tok[e2][p2] = t; g_wgt[e2][p2] = w2; g_slot[e2][p2] = 1;
    }
}

// rswaf basis expansion: dst[idx*8+g] = 1 - tanh((src[idx]-grid[g])*0.5)^2
// WHICH==0 : src = param (hidden), dst = g_b1, no row guard   (cols = H)
// WHICH==1 : src = g_mid slab z,   dst = g_b2 slab z, guard rows >= cnt (cols = F2)
template<int WHICH>
__global__ void basis_kernel(const float* __restrict__ src_param) {
    int idx = blockIdx.x * blockDim.x + threadIdx.x;   // element index over T*cols
    const float* src; float* dst;
    if (WHICH == 0) {
        src = src_param;
        dst = g_b1;
    } else {
        int z = blockIdx.z;
        int row = idx / F2;
        if (row >= g_cnt[NM + z]) return;
        src = g_mid + (size_t)z * T * F;
        dst = g_b2  + (size_t)z * T * FG2;
    }
    float x = src[idx];
    float r[8];
    #pragma unroll
    for (int i = 0; i < 8; i++) {
        float d = (x - (-1.2f + 0.2f * (float)i)) * 0.5f;
        float th = tanhf(d);
        r[i] = 1.0f - th * th;
    }
    float* d4 = dst + (size_t)idx * 8;
    ((float4*)d4)[0] = make_float4(r[0], r[1], r[2], r[3]);
    ((float4*)d4)[1] = make_float4(r[4], r[5], r[6], r[7]);
}

// ---------------- GEMM: C[i,n] = sum_k A[i,k] * B[n,k]  (both K-major) ----------
// 128x128 tile, BK=8, 256 threads, 8x8 per-thread register blocking.
// blockIdx.x = col tile, blockIdx.y = row tile (over gathered tokens), blockIdx.z = expert
// MODE 0: C = gelu(acc + bias)           -> g_mid slab z  (MLP fc1)
// MODE 1: C = acc                        -> g_mid slab z  (KAN sp1 -> k1)
// MODE 2: out = wgt * (acc [+ bias])     -> g_outslot[slot][tok]  (fc2 / sp2)
template<int MODE>
__global__ __launch_bounds__(256, 2)
void gemm_kernel(const float* __restrict__ Abase, size_t Aslab, int lda, int gather, int eoff,
                 const float* __restrict__ Bbase, size_t Bslab,
                 const float* __restrict__ biasbase, int biasslab,
                 float* __restrict__ Cbase, size_t Cslab, int ldc,
                 int K) {
    int z = blockIdx.z;
    int expert = eoff + z;
    int cnt = g_cnt[expert];
    int by = blockIdx.y, bx = blockIdx.x;
    if (by * 128 >= cnt) return;

    __shared__ float As[8 * 132];
    __shared__ float Bs[8 * 132];

    const float* A = Abase + (size_t)z * Aslab;
    const float* B = Bbase + (size_t)z * Bslab;

    int tid = threadIdx.x;
    int j  = tid * 4;
    int tr = j >> 3;        // tile row 0..127
    int tk = j & 7;         // 0 or 4

    const float* Arow;
    if (gather) {
        int gi = by * 128 + tr;
        if (gi >= cnt) gi = cnt - 1;
        Arow = A + (size_t)g_tok[expert][gi] * lda;
    } else {
        Arow = A + (size_t)(by * 128 + tr) * lda;
    }
    const float* Brow = B + (size_t)(bx * 128 + tr) * K;

    int rm = tid >> 4, rn = tid & 15;
    int rm8 = rm * 8, rn8 = rn * 8;

    float acc[8][8];
    #pragma unroll
    for (int ii = 0; ii < 8; ii++)
        #pragma unroll
        for (int jj = 0; jj < 8; jj++) acc[ii][jj] = 0.f;

    for (int k0 = 0; k0 < K; k0 += 8) {
        float4 av = *reinterpret_cast<const float4*>(Arow + k0 + tk);
        float4 bv = *reinterpret_cast<const float4*>(Brow + k0 + tk);
        __syncthreads();
        As[(tk + 0) * 132 + tr] = av.x;
        As[(tk + 1) * 132 + tr] = av.y;
        As[(tk + 2) * 132 + tr] = av.z;
        As[(tk + 3) * 132 + tr] = av.w;
        Bs[(tk + 0) * 132 + tr] = bv.x;
        Bs[(tk + 1) * 132 + tr] = bv.y;
        Bs[(tk + 2) * 132 + tr] = bv.z;
        Bs[(tk + 3) * 132 + tr] = bv.w;
        __syncthreads();
        #pragma unroll
        for (int kk = 0; kk < 8; kk++) {
            float a[8], b[8];
            *(float4*)&a[0] = *(const float4*)&As[kk * 132 + rm8];
            *(float4*)&a[4] = *(const float4*)&As[kk * 132 + rm8 + 4];
            *(float4*)&b[0] = *(const float4*)&Bs[kk * 132 + rn8];
            *(float4*)&b[4] = *(const float4*)&Bs[kk * 132 + rn8 + 4];
            #pragma unroll
            for (int ii = 0; ii < 8; ii++)
                #pragma unroll
                for (int jj = 0; jj < 8; jj++)
                    acc[ii][jj] += a[ii] * b[jj];
        }
    }

    int i0 = by * 128 + rm8;
    int n0 = bx * 128 + rn8;

    if (MODE == 0) {
        const float* bias = biasbase + (size_t)z * biasslab;
        float* C = Cbase + (size_t)z * Cslab;
        #pragma unroll
        for (int ii = 0; ii < 8; ii++) {
            int i = i0 + ii;
            if (i < cnt) {
                #pragma unroll
                for (int jj = 0; jj < 8; jj++) {
                    int n = n0 + jj;
                    float v = acc[ii][jj] + bias[n];
                    C[(size_t)i * ldc + n] = 0.5f * v * (1.0f + erff(v * 0.70710678118654752f));
                }
            }
        }
    } else if (MODE == 1) {
        float* C = Cbase + (size_t)z * Cslab;
        #pragma unroll
        for (int ii = 0; ii < 8; ii++) {
            int i = i0 + ii;
            if (i < cnt) {
                #pragma unroll
                for (int jj = 0; jj < 8; jj++)
                    C[(size_t)i * ldc + n0 + jj] = acc[ii][jj];
            }
        }
    } else {
        const float* bias = biasbase ? (biasbase + (size_t)z * biasslab) : nullptr;
        #pragma unroll
        for (int ii = 0; ii < 8; ii++) {
            int i = i0 + ii;
            if (i < cnt) {
                int   t = g_tok[expert][i];
                float w = g_wgt[expert][i];
                int   s = g_slot[expert][i];
                float* o = &g_outslot[s][(size_t)t * H];
                #pragma unroll
                for (int jj = 0; jj < 8; jj++) {
                    int n = n0 + jj;
                    float v = acc[ii][jj];
                    if (bias) v += bias[n];
                    o[n] = w * v;
                }
            }
        }
    }
}

__global__ void combine_kernel(float* __restrict__ out) {
    int i = blockIdx.x * blockDim.x + threadIdx.x;   // over T*H/4
    float4 a = ((const float4*)g_outslot[0])[i];
    float4 b = ((const float4*)g_outslot[1])[i];
    ((float4*)out)[i] = make_float4(a.x + b.x, a.y + b.y, a.z + b.z, a.w + b.w);
}

// ---------------- launch --------------------------------------------------------
extern "C" void kernel_launch(void* const* d_in, const int* in_sizes, int n_in,
                              void* d_out, int out_size) {
    const float* hs     = (const float*)d_in[0];
    const float* gate_w = (const float*)d_in[1];
    const float* fc1_w  = (const float*)d_in[2];
    const float* fc1_b  = (const float*)d_in[3];
    const float* fc2_w  = (const float*)d_in[4];
    const float* fc2_b  = (const float*)d_in[5];
    const float* sp1_w  = (const float*)d_in[6];
    const float* sp2_w  = (const float*)d_in[7];
    float* out = (float*)d_out;

    float *p_b1 = nullptr, *p_mid = nullptr, *p_b2 = nullptr;
    cudaGetSymbolAddress((void**)&p_b1,  g_b1);
    cudaGetSymbolAddress((void**)&p_mid, g_mid);
    cudaGetSymbolAddress((void**)&p_b2,  g_b2);

    zero_cnt_kernel<<<1, 32>>>();
    router_kernel<<<T, 256>>>(hs, gate_w);
    basis_kernel<0><<<(T * H) / 256, 256>>>(hs);

    // MLP experts 0..3 (routing experts 0..3), batched over blockIdx.z
    gemm_kernel<0><<<dim3(F / 128, 16, NM), 256>>>(
        hs, 0, H, /*gather=*/1, /*eoff=*/0,
        fc1_w, (size_t)F * H,
        fc1_b, F,
        p_mid, (size_t)T * F, F,
        H);
    gemm_kernel<2><<<dim3(H / 128, 16, NM), 256>>>(
        p_mid, (size_t)T * F, F, /*gather=*/0, /*eoff=*/0,
        fc2_w, (size_t)H * F,
        fc2_b, H,
        nullptr, 0, 0,
        F);

    // KAN experts 0..3 (routing experts 4..7)
    gemm_kernel<1><<<dim3(F2 / 128, 16, NM), 256>>>(
        p_b1, 0, HG, /*gather=*/1, /*eoff=*/NM,
        sp1_w, (size_t)F2 * HG,
        nullptr, 0,
        p_mid, (size_t)T * F, F2,
        HG);
    basis_kernel<1><<<dim3((T * F2) / 256, 1, NM), 256>>>(nullptr);
    gemm_kernel<2><<<dim3(H / 128, 16, NM), 256>>>(
        p_b2, (size_t)T * FG2, FG2, /*gather=*/0, /*eoff=*/NM,
        sp2_w, (size_t)H * FG2,
        nullptr, 0,
        nullptr, 0, 0,
        FG2);

    combine_kernel<<<(T * H / 4) / 256, 256>>>(out);
}

// round 3
// speedup vs baseline: 2.8507x; 2.8507x over previous
#include <cuda_runtime.h>
#include <cstdint>
#include <math.h>

#define T 2048
#define H 1024
#define F 4096
#define E 8
#define NM 4
#define G 8
#define HG (H*G)      /* 8192  */
#define F2 (F/2)      /* 2048  */
#define FG2 (F2*G)    /* 16384 */

// ---------------- scratch (device globals; no allocation allowed) -------------
__device__ float g_b1[(size_t)T * HG];               // rswaf(hidden)
__device__ float g_mid[(size_t)NM * T * F];          // per-expert mid (gelu(fc1) or k1)
__device__ float g_b2[(size_t)NM * T * FG2];         // per-expert rswaf(k1)
__device__ float g_outslot[2][(size_t)T * H];        // per-(token,slot) weighted outputs
__device__ int   g_tok[E][T];
__device__ float g_wgt[E][T];
__device__ int   g_slot[E][T];
__device__ int   g_cnt[E];

// ---------------- helpers ------------------------------------------------------
__device__ __forceinline__ uint32_t f2tf32(float x) {
    uint32_t r; asm("cvt.rna.tf32.f32 %0, %1;" : "=r"(r) : "f"(x)); return r;
}
__device__ __forceinline__ void mma_tf32(float* c, uint32_t a0, uint32_t a1,
                                         uint32_t a2, uint32_t a3,
                                         uint32_t b0, uint32_t b1) {
    asm volatile("mma.sync.aligned.m16n8k8.row.col.f32.tf32.tf32.f32 "
        "{%0,%1,%2,%3},{%4,%5,%6,%7},{%8,%9},{%0,%1,%2,%3};"
        : "+f"(c[0]), "+f"(c[1]), "+f"(c[2]), "+f"(c[3])
        : "r"(a0), "r"(a1), "r"(a2), "r"(a3), "r"(b0), "r"(b1));
}
// swizzled word index for element (row 0..127, k 0..31) in a 128x32 tile
__device__ __forceinline__ int swz(int r, int k) {
    return r * 32 + ((((k >> 2) ^ (r & 7)) << 2) | (k & 3));
}

// ---------------- small kernels ------------------------------------------------
__global__ void zero_cnt_kernel() {
    if (threadIdx.x < E) g_cnt[threadIdx.x] = 0;
}

__global__ void router_kernel(const float* __restrict__ hs, const float* __restrict__ gw) {
    int t = blockIdx.x;
    int warp = threadIdx.x >> 5, lane = threadIdx.x & 31;
    const float* x = hs + (size_t)t * H;
    const float* g = gw + (size_t)warp * H;
    float s = 0.f;
    for (int k = lane; k < H; k += 32) s += x[k] * g[k];
    #pragma unroll
    for (int o = 16; o; o >>= 1) s += __shfl_xor_sync(0xFFFFFFFFu, s, o);
    __shared__ float logits[E];
    if (lane == 0) logits[warp] = s;
    __syncthreads();
    if (threadIdx.x == 0) {
        float l1 = -1e30f, l2 = -1e30f; int e1 = 0, e2 = 0;
        #pragma unroll
        for (int e = 0; e < E; e++) {
            float v = logits[e];
            if (v > l1) { l2 = l1; e2 = e1; l1 = v; e1 = e; }
            else if (v > l2) { l2 = v; e2 = e; }
        }
        float r  = expf(l2 - l1);
        float w1 = 1.0f / (1.0f + r);
        float w2 = r * w1;
        int p1 = atomicAdd(&g_cnt[e1], 1);
        g_tok[e1][p1] = t; g_wgt[e1][p1] = w1; g_slot[e1][p1] = 0;
        int p2 = atomicAdd(&g_cnt[e2], 1);
        g_tok[e2][p2] = t; g_wgt[e2][p2] = w2; g_slot[e2][p2] = 1;
    }
}

template<int WHICH>
__global__ void basis_kernel(const float* __restrict__ src_param) {
    int idx = blockIdx.x * blockDim.x + threadIdx.x;
    const float* src; float* dst;
    if (WHICH == 0) {
        src = src_param; dst = g_b1;
    } else {
        int z = blockIdx.z;
        int row = idx / F2;
        if (row >= g_cnt[NM + z]) return;
        src = g_mid + (size_t)z * T * F;
        dst = g_b2  + (size_t)z * T * FG2;
    }
    float x = src[idx];
    float r[8];
    #pragma unroll
    for (int i = 0; i < 8; i++) {
        float d = (x - (-1.2f + 0.2f * (float)i)) * 0.5f;
        float th = tanhf(d);
        r[i] = 1.0f - th * th;
    }
    float* d4 = dst + (size_t)idx * 8;
    ((float4*)d4)[0] = make_float4(r[0], r[1], r[2], r[3]);
    ((float4*)d4)[1] = make_float4(r[4], r[5], r[6], r[7]);
}

// ================= tf32 mma.sync GEMM ==========================================
// C[i,n] = sum_k A[i,k]*B[n,k]; K-major fp32 inputs, tf32 HMMA, fp32 accumulate.
// 128x128 tile, BK=32, 256 threads (8 warps, 2x4), double-buffered swizzled SMEM.
// MODE 0: C = gelu(acc + bias) -> g_mid   MODE 1: C = acc -> g_mid
// MODE 2: out = wgt * (acc [+bias]) -> g_outslot[slot][tok]
#define SMEM_WORDS (4 * 4096)   /* As0 As1 Bs0 Bs1, 16KB each */
#define SMEM_BYTES (SMEM_WORDS * 4)

template<int MODE>
__global__ __launch_bounds__(256, 1)
void mma_gemm(const float* __restrict__ Abase, size_t Aslab, int lda, int gather, int eoff,
              const float* __restrict__ Bbase, size_t Bslab,
              const float* __restrict__ biasbase, int biasslab,
              float* __restrict__ Cbase, size_t Cslab, int ldc, int K) {
    int z = blockIdx.z, expert = eoff + z;
    int cnt = g_cnt[expert];
    int by = blockIdx.y, bx = blockIdx.x;
    if (by * 128 >= cnt) return;

    extern __shared__ __align__(16) uint32_t smw[];
    uint32_t* Abuf[2] = { smw,        smw + 4096 };
    uint32_t* Bbuf[2] = { smw + 8192, smw + 12288 };

    const float* A = Abase + (size_t)z * Aslab;
    const float* B = Bbase + (size_t)z * Bslab;

    int tid = threadIdx.x;
    // ---- loader mapping: c = k-group (4 floats), rows r0+32j ----
    int c  = tid & 7;
    int r0 = tid >> 3;
    const float* aptr[4]; const float* bptr[4];
    int stw[4];
    #pragma unroll
    for (int j = 0; j < 4; j++) {
        int row = r0 + j * 32;
        int arow;
        if (gather) {
            int gi = by * 128 + row;
            if (gi >= cnt) gi = cnt - 1;
            arow = g_tok[expert][gi];
        } else {
            arow = by * 128 + row;
        }
        aptr[j] = A + (size_t)arow * lda + c * 4;
        bptr[j] = B + (size_t)(bx * 128 + row) * K + c * 4;
        stw[j] = row * 32 + ((c ^ (row & 7)) << 2);
    }

    int wid = tid >> 5, lane = tid & 31;
    int wm = wid >> 2, wn = wid & 3;
    int gp = lane >> 2, tig = lane & 3;

    float acc[4][4][4];
    #pragma unroll
    for (int mt = 0; mt < 4; mt++)
        #pragma unroll
        for (int nt = 0; nt < 4; nt++)
            #pragma unroll
            for (int q = 0; q < 4; q++) acc[mt][nt][q] = 0.f;

    int nch = K >> 5;
    float4 av[4], bv[4];

    // prologue: load + stage chunk 0
    #pragma unroll
    for (int j = 0; j < 4; j++) { av[j] = *(const float4*)(aptr[j]); bv[j] = *(const float4*)(bptr[j]); }
    #pragma unroll
    for (int j = 0; j < 4; j++) {
        uint4 ua = make_uint4(f2tf32(av[j].x), f2tf32(av[j].y), f2tf32(av[j].z), f2tf32(av[j].w));
        uint4 ub = make_uint4(f2tf32(bv[j].x), f2tf32(bv[j].y), f2tf32(bv[j].z), f2tf32(bv[j].w));
        *(uint4*)&Abuf[0][stw[j]] = ua;
        *(uint4*)&Bbuf[0][stw[j]] = ub;
    }
    __syncthreads();

    for (int i = 0; i < nch; i++) {
        int s = i & 1;
        if (i + 1 < nch) {
            size_t k0 = (size_t)(i + 1) << 5;
            #pragma unroll
            for (int j = 0; j < 4; j++) {
                av[j] = *(const float4*)(aptr[j] + k0);
                bv[j] = *(const float4*)(bptr[j] + k0);
            }
        }
        // ---- compute on buffer s ----
        const uint32_t* As = Abuf[s];
        const uint32_t* Bs = Bbuf[s];
        #pragma unroll
        for (int k8 = 0; k8 < 4; k8++) {
            int kb = k8 * 8 + tig;
            uint32_t bfr[4][2];
            #pragma unroll
            for (int nt = 0; nt < 4; nt++) {
                int nr = wn * 32 + nt * 8 + gp;
                bfr[nt][0] = Bs[swz(nr, kb)];
                bfr[nt][1] = Bs[swz(nr, kb + 4)];
            }
            #pragma unroll
            for (int mt = 0; mt < 4; mt++) {
                int r1 = wm * 64 + mt * 16 + gp;
                uint32_t a0 = As[swz(r1,     kb)];
                uint32_t a1 = As[swz(r1 + 8, kb)];
                uint32_t a2 = As[swz(r1,     kb + 4)];
                uint32_t a3 = As[swz(r1 + 8, kb + 4)];
                #pragma unroll
                for (int nt = 0; nt < 4; nt++)
                    mma_tf32(acc[mt][nt], a0, a1, a2, a3, bfr[nt][0], bfr[nt][1]);
            }
        }
        __syncthreads();
        if (i + 1 < nch) {
            int s2 = s ^ 1;
            #pragma unroll
            for (int j = 0; j < 4; j++) {
                uint4 ua = make_uint4(f2tf32(av[j].x), f2tf32(av[j].y), f2tf32(av[j].z), f2tf32(av[j].w));
                uint4 ub = make_uint4(f2tf32(bv[j].x), f2tf32(bv[j].y), f2tf32(bv[j].z), f2tf32(bv[j].w));
                *(uint4*)&Abuf[s2][stw[j]] = ua;
                *(uint4*)&Bbuf[s2][stw[j]] = ub;
            }
            __syncthreads();
        }
    }

    // ---- epilogue ----
    const float* bias = nullptr;
    if (MODE == 0) bias = biasbase + (size_t)z * biasslab;
    if (MODE == 2 && biasbase) bias = biasbase + (size_t)z * biasslab;

    #pragma unroll
    for (int mt = 0; mt < 4; mt++) {
        #pragma unroll
        for (int half = 0; half < 2; half++) {
            int row = by * 128 + wm * 64 + mt * 16 + gp + half * 8;
            if (row >= cnt) continue;
            float* dst;
            float wv = 1.f;
            if (MODE == 0 || MODE == 1) {
                dst = Cbase + (size_t)z * Cslab + (size_t)row * ldc;
            } else {
                int   t  = g_tok[expert][row];
                int   sl = g_slot[expert][row];
                wv = g_wgt[expert][row];
                dst = &g_outslot[sl][(size_t)t * H];
            }
            #pragma unroll
            for (int nt = 0; nt < 4; nt++) {
                int col = bx * 128 + wn * 32 + nt * 8 + 2 * tig;
                float v0 = acc[mt][nt][half * 2];
                float v1 = acc[mt][nt][half * 2 + 1];
                if (MODE == 0) {
                    v0 += bias[col];     v1 += bias[col + 1];
                    v0 = 0.5f * v0 * (1.0f + erff(v0 * 0.70710678118654752f));
                    v1 = 0.5f * v1 * (1.0f + erff(v1 * 0.70710678118654752f));
                } else if (MODE == 2) {
                    if (bias) { v0 += bias[col]; v1 += bias[col + 1]; }
                    v0 *= wv; v1 *= wv;
                }
                *(float2*)(dst + col) = make_float2(v0, v1);
            }
        }
    }
}

__global__ void combine_kernel(float* __restrict__ out) {
    int i = blockIdx.x * blockDim.x + threadIdx.x;
    float4 a = ((const float4*)g_outslot[0])[i];
    float4 b = ((const float4*)g_outslot[1])[i];
    ((float4*)out)[i] = make_float4(a.x + b.x, a.y + b.y, a.z + b.z, a.w + b.w);
}

// ---------------- launch --------------------------------------------------------
extern "C" void kernel_launch(void* const* d_in, const int* in_sizes, int n_in,
                              void* d_out, int out_size) {
    const float* hs     = (const float*)d_in[0];
    const float* gate_w = (const float*)d_in[1];
    const float* fc1_w  = (const float*)d_in[2];
    const float* fc1_b  = (const float*)d_in[3];
    const float* fc2_w  = (const float*)d_in[4];
    const float* fc2_b  = (const float*)d_in[5];
    const float* sp1_w  = (const float*)d_in[6];
    const float* sp2_w  = (const float*)d_in[7];
    float* out = (float*)d_out;

    float *p_b1 = nullptr, *p_mid = nullptr, *p_b2 = nullptr;
    cudaGetSymbolAddress((void**)&p_b1,  g_b1);
    cudaGetSymbolAddress((void**)&p_mid, g_mid);
    cudaGetSymbolAddress((void**)&p_b2,  g_b2);

    cudaFuncSetAttribute(mma_gemm<0>, cudaFuncAttributeMaxDynamicSharedMemorySize, SMEM_BYTES);
    cudaFuncSetAttribute(mma_gemm<1>, cudaFuncAttributeMaxDynamicSharedMemorySize, SMEM_BYTES);
    cudaFuncSetAttribute(mma_gemm<2>, cudaFuncAttributeMaxDynamicSharedMemorySize, SMEM_BYTES);

    zero_cnt_kernel<<<1, 32>>>();
    router_kernel<<<T, 256>>>(hs, gate_w);
    basis_kernel<0><<<(T * H) / 256, 256>>>(hs);

    // MLP experts (routing experts 0..3)
    mma_gemm<0><<<dim3(F / 128, 16, NM), 256, SMEM_BYTES>>>(
        hs, 0, H, /*gather=*/1, /*eoff=*/0,
        fc1_w, (size_t)F * H,
        fc1_b, F,
        p_mid, (size_t)T * F, F,
        H);
    mma_gemm<2><<<dim3(H / 128, 16, NM), 256, SMEM_BYTES>>>(
        p_mid, (size_t)T * F, F, /*gather=*/0, /*eoff=*/0,
        fc2_w, (size_t)H * F,
        fc2_b, H,
        nullptr, 0, 0,
        F);

    // KAN experts (routing experts 4..7)
    mma_gemm<1><<<dim3(F2 / 128, 16, NM), 256, SMEM_BYTES>>>(
        p_b1, 0, HG, /*gather=*/1, /*eoff=*/NM,
        sp1_w, (size_t)F2 * HG,
        nullptr, 0,
        p_mid, (size_t)T * F, F2,
        HG);
    basis_kernel<1><<<dim3((T * F2) / 256, 1, NM), 256>>>(nullptr);
    mma_gemm<2><<<dim3(H / 128, 16, NM), 256, SMEM_BYTES>>>(
        p_b2, (size_t)T * FG2, FG2, /*gather=*/0, /*eoff=*/NM,
        sp2_w, (size_t)H * FG2,
        nullptr, 0,
        nullptr, 0, 0,
        FG2);

    combine_kernel<<<(T * H / 4) / 256, 256>>>(out);
}

// round 4
// speedup vs baseline: 3.8772x; 1.3601x over previous
#include <cuda_runtime.h>
#include <cstdint>
#include <math.h>

#define T 2048
#define H 1024
#define F 4096
#define E 8
#define NM 4
#define G 8
#define HG (H*G)      /* 8192  */
#define F2 (F/2)      /* 2048  */
#define FG2 (F2*G)    /* 16384 */

// ---------------- scratch (device globals; no allocation allowed) -------------
__device__ float g_hsr[(size_t)T * H];               // tf32-rounded hidden
__device__ float g_b1[(size_t)T * HG];               // rswaf(hidden), tf32-rounded
__device__ float g_mid[(size_t)NM * T * F];          // gelu(fc1) (rounded) or k1 (raw)
__device__ float g_b2[(size_t)NM * T * FG2];         // rswaf(k1), tf32-rounded
__device__ float g_outslot[2][(size_t)T * H];        // per-(token,slot) weighted outputs
__device__ int   g_tok[E][T];
__device__ float g_wgt[E][T];
__device__ int   g_slot[E][T];
__device__ int   g_cnt[E];

// ---------------- helpers ------------------------------------------------------
__device__ __forceinline__ uint32_t f2tf32(float x) {
    uint32_t r; asm("cvt.rna.tf32.f32 %0, %1;" : "=r"(r) : "f"(x)); return r;
}
__device__ __forceinline__ float round_tf32(float x) {
    return __uint_as_float(f2tf32(x));
}
__device__ __forceinline__ void mma_tf32(float* c, uint32_t a0, uint32_t a1,
                                         uint32_t a2, uint32_t a3,
                                         uint32_t b0, uint32_t b1) {
    asm volatile("mma.sync.aligned.m16n8k8.row.col.f32.tf32.tf32.f32 "
        "{%0,%1,%2,%3},{%4,%5,%6,%7},{%8,%9},{%0,%1,%2,%3};"
        : "+f"(c[0]), "+f"(c[1]), "+f"(c[2]), "+f"(c[3])
        : "r"(a0), "r"(a1), "r"(a2), "r"(a3), "r"(b0), "r"(b1));
}
__device__ __forceinline__ uint32_t smem_u32(const void* p) {
    uint32_t a;
    asm("{ .reg .u64 t; cvta.to.shared.u64 t, %1; cvt.u32.u64 %0, t; }" : "=r"(a) : "l"(p));
    return a;
}
#define CP_ASYNC16(dst, src) \
    asm volatile("cp.async.cg.shared.global [%0], [%1], 16;" :: "r"(dst), "l"(src))
#define CP_COMMIT()  asm volatile("cp.async.commit_group;" ::: "memory")
#define CP_WAIT0()   asm volatile("cp.async.wait_group 0;" ::: "memory")

// ---------------- small kernels ------------------------------------------------
__global__ void zero_cnt_kernel() {
    if (threadIdx.x < E) g_cnt[threadIdx.x] = 0;
}

__global__ void round_hs_kernel(const float* __restrict__ hs) {
    int i = blockIdx.x * blockDim.x + threadIdx.x;   // over T*H/4
    float4 v = ((const float4*)hs)[i];
    ((float4*)g_hsr)[i] = make_float4(round_tf32(v.x), round_tf32(v.y),
                                      round_tf32(v.z), round_tf32(v.w));
}

__global__ void router_kernel(const float* __restrict__ hs, const float* __restrict__ gw) {
    int t = blockIdx.x;
    int warp = threadIdx.x >> 5, lane = threadIdx.x & 31;
    const float* x = hs + (size_t)t * H;
    const float* g = gw + (size_t)warp * H;
    float s = 0.f;
    for (int k = lane; k < H; k += 32) s += x[k] * g[k];
    #pragma unroll
    for (int o = 16; o; o >>= 1) s += __shfl_xor_sync(0xFFFFFFFFu, s, o);
    __shared__ float logits[E];
    if (lane == 0) logits[warp] = s;
    __syncthreads();
    if (threadIdx.x == 0) {
        float l1 = -1e30f, l2 = -1e30f; int e1 = 0, e2 = 0;
        #pragma unroll
        for (int e = 0; e < E; e++) {
            float v = logits[e];
            if (v > l1) { l2 = l1; e2 = e1; l1 = v; e1 = e; }
            else if (v > l2) { l2 = v; e2 = e; }
        }
        float r  = expf(l2 - l1);
        float w1 = 1.0f / (1.0f + r);
        float w2 = r * w1;
        int p1 = atomicAdd(&g_cnt[e1], 1);
        g_tok[e1][p1] = t; g_wgt[e1][p1] = w1; g_slot[e1][p1] = 0;
        int p2 = atomicAdd(&g_cnt[e2], 1);
        g_tok[e2][p2] = t; g_wgt[e2][p2] = w2; g_slot[e2][p2] = 1;
    }
}

// rswaf basis; output pre-rounded to tf32 (it is only ever a GEMM A operand)
template<int WHICH>
__global__ void basis_kernel(const float* __restrict__ src_param) {
    int idx = blockIdx.x * blockDim.x + threadIdx.x;
    const float* src; float* dst;
    if (WHICH == 0) {
        src = src_param; dst = g_b1;
    } else {
        int z = blockIdx.z;
        int row = idx / F2;
        if (row >= g_cnt[NM + z]) return;
        src = g_mid + (size_t)z * T * F;
        dst = g_b2  + (size_t)z * T * FG2;
    }
    float x = src[idx];
    float r[8];
    #pragma unroll
    for (int i = 0; i < 8; i++) {
        float d = (x - (-1.2f + 0.2f * (float)i)) * 0.5f;
        float th = tanhf(d);
        r[i] = round_tf32(1.0f - th * th);
    }
    float* d4 = dst + (size_t)idx * 8;
    ((float4*)d4)[0] = make_float4(r[0], r[1], r[2], r[3]);
    ((float4*)d4)[1] = make_float4(r[4], r[5], r[6], r[7]);
}

// ================= tf32 mma.sync GEMM v2 =======================================
// 128x128 tile, BK=32, 128 threads (4 warps 2x2, warp tile 64x64), 2 CTAs/SM.
// A pre-rounded tf32 -> staged via cp.async. B = weights, LDG->cvt->STS.
// MODE 0: C = round(gelu(acc + bias)) -> g_mid   MODE 1: C = acc (raw) -> g_mid
// MODE 2: out = wgt * (acc [+bias]) -> g_outslot[slot][tok]
#define STAGE_W 4096                 /* 128x32 words = 16KB */
#define SMEM_BYTES (4 * STAGE_W * 4) /* A0 A1 B0 B1 = 64KB  */

template<int MODE>
__global__ __launch_bounds__(128, 2)
void mma_gemm(const float* __restrict__ Abase, size_t Aslab, int lda, int gather, int eoff,
              const float* __restrict__ Bbase, size_t Bslab,
              const float* __restrict__ biasbase, int biasslab,
              float* __restrict__ Cbase, size_t Cslab, int ldc, int K) {
    int z = blockIdx.z, expert = eoff + z;
    int cnt = g_cnt[expert];
    int by = blockIdx.y, bx = blockIdx.x;
    if (by * 128 >= cnt) return;

    extern __shared__ __align__(16) uint32_t smw[];
    uint32_t smem_base = smem_u32(smw);

    const float* A = Abase + (size_t)z * Aslab;
    const float* B = Bbase + (size_t)z * Bslab;

    int tid = threadIdx.x;
    int c  = tid & 7;        // float4 column within 32-float chunk
    int r0 = tid >> 3;       // 0..15; rows r0 + 16j
    // loader addresses (loop-invariant)
    uint32_t a_off[8]; uint32_t b_off[8];
    uint32_t st_dst[8];      // word offset within a stage
    #pragma unroll
    for (int j = 0; j < 8; j++) {
        int row = r0 + 16 * j;
        int arow;
        if (gather) {
            int gi = by * 128 + row;
            if (gi >= cnt) gi = cnt - 1;
            arow = g_tok[expert][gi];
        } else {
            arow = by * 128 + row;
        }
        a_off[j] = (uint32_t)arow * (uint32_t)lda * 4u + c * 16u;
        b_off[j] = (uint32_t)(bx * 128 + row) * (uint32_t)K * 4u + c * 16u;
        st_dst[j] = row * 32 + ((c ^ (row & 7)) << 2);
    }

    int wid = tid >> 5, lane = tid & 31;
    int wm = wid >> 1, wn = wid & 1;
    int gp = lane >> 2, tig = lane & 3;

    float acc[4][8][4];
    #pragma unroll
    for (int mt = 0; mt < 4; mt++)
        #pragma unroll
        for (int nt = 0; nt < 8; nt++)
            #pragma unroll
            for (int q = 0; q < 4; q++) acc[mt][nt][q] = 0.f;

    int nch = K >> 5;

    // ---- prologue: stage chunk 0 ----
    #pragma unroll
    for (int j = 0; j < 8; j++)
        CP_ASYNC16(smem_base + st_dst[j] * 4, (const char*)A + a_off[j]);
    CP_COMMIT();
    {
        float4 bv[8];
        #pragma unroll
        for (int j = 0; j < 8; j++) bv[j] = *(const float4*)((const char*)B + b_off[j]);
        #pragma unroll
        for (int j = 0; j < 8; j++) {
            uint4 u = make_uint4(f2tf32(bv[j].x), f2tf32(bv[j].y), f2tf32(bv[j].z), f2tf32(bv[j].w));
            *(uint4*)&smw[2 * STAGE_W + st_dst[j]] = u;
        }
    }
    CP_WAIT0();
    __syncthreads();

    for (int i = 0; i < nch; i++) {
        int s = i & 1;
        float4 bv[8];
        if (i + 1 < nch) {
            uint32_t k0 = (uint32_t)(i + 1) * 128u;   // byte offset
            #pragma unroll
            for (int j = 0; j < 8; j++)
                bv[j] = *(const float4*)((const char*)B + b_off[j] + k0);
            uint32_t dst_a = smem_base + (s ^ 1) * (STAGE_W * 4);
            #pragma unroll
            for (int j = 0; j < 8; j++)
                CP_ASYNC16(dst_a + st_dst[j] * 4, (const char*)A + a_off[j] + k0);
            CP_COMMIT();
        }

        // ---- compute on stage s ----
        const uint32_t* As = smw + s * STAGE_W;
        const uint32_t* Bs = smw + 2 * STAGE_W + s * STAGE_W;
        #pragma unroll
        for (int k8 = 0; k8 < 4; k8++) {
            int o0 = (((k8 * 2 + 0) ^ gp) << 2) + tig;
            int o1 = (((k8 * 2 + 1) ^ gp) << 2) + tig;
            uint32_t bf[8][2];
            #pragma unroll
            for (int nt = 0; nt < 8; nt++) {
                int rb = (wn * 64 + nt * 8 + gp) * 32;
                bf[nt][0] = Bs[rb + o0];
                bf[nt][1] = Bs[rb + o1];
            }
            #pragma unroll
            for (int mt = 0; mt < 4; mt++) {
                int ra = (wm * 64 + mt * 16 + gp) * 32;
                uint32_t a0 = As[ra + o0];
                uint32_t a1 = As[ra + 256 + o0];
                uint32_t a2 = As[ra + o1];
                uint32_t a3 = As[ra + 256 + o1];
                #pragma unroll
                for (int nt = 0; nt < 8; nt++)
                    mma_tf32(acc[mt][nt], a0, a1, a2, a3, bf[nt][0], bf[nt][1]);
            }
        }

        if (i + 1 < nch) {
            uint32_t* Bd = smw + 2 * STAGE_W + (s ^ 1) * STAGE_W;
            #pragma unroll
            for (int j = 0; j < 8; j++) {
                uint4 u = make_uint4(f2tf32(bv[j].x), f2tf32(bv[j].y), f2tf32(bv[j].z), f2tf32(bv[j].w));
                *(uint4*)&Bd[st_dst[j]] = u;
            }
            CP_WAIT0();
        }
        __syncthreads();
    }

    // ---- epilogue ----
    const float* bias = nullptr;
    if (MODE == 0) bias = biasbase + (size_t)z * biasslab;
    if (MODE == 2 && biasbase) bias = biasbase + (size_t)z * biasslab;

    #pragma unroll
    for (int mt = 0; mt < 4; mt++) {
        #pragma unroll
        for (int half = 0; half < 2; half++) {
            int row = by * 128 + wm * 64 + mt * 16 + gp + half * 8;
            if (row >= cnt) continue;
            float* dst;
            float wv = 1.f;
            if (MODE == 0 || MODE == 1) {
                dst = Cbase + (size_t)z * Cslab + (size_t)row * ldc;
            } else {
                int   t  = g_tok[expert][row];
                int   sl = g_slot[expert][row];
                wv = g_wgt[expert][row];
                dst = &g_outslot[sl][(size_t)t * H];
            }
            #pragma unroll
            for (int nt = 0; nt < 8; nt++) {
                int col = bx * 128 + wn * 64 + nt * 8 + 2 * tig;
                float v0 = acc[mt][nt][half * 2];
                float v1 = acc[mt][nt][half * 2 + 1];
                if (MODE == 0) {
                    v0 += bias[col];     v1 += bias[col + 1];
                    v0 = 0.5f * v0 * (1.0f + erff(v0 * 0.70710678118654752f));
                    v1 = 0.5f * v1 * (1.0f + erff(v1 * 0.70710678118654752f));
                    v0 = round_tf32(v0); v1 = round_tf32(v1);  // mid is next GEMM's A
                } else if (MODE == 2) {
                    if (bias) { v0 += bias[col]; v1 += bias[col + 1]; }
                    v0 *= wv; v1 *= wv;
                }
                *(float2*)(dst + col) = make_float2(v0, v1);
            }
        }
    }
}

__global__ void combine_kernel(float* __restrict__ out) {
    int i = blockIdx.x * blockDim.x + threadIdx.x;
    float4 a = ((const float4*)g_outslot[0])[i];
    float4 b = ((const float4*)g_outslot[1])[i];
    ((float4*)out)[i] = make_float4(a.x + b.x, a.y + b.y, a.z + b.z, a.w + b.w);
}

// ---------------- launch --------------------------------------------------------
extern "C" void kernel_launch(void* const* d_in, const int* in_sizes, int n_in,
                              void* d_out, int out_size) {
    const float* hs     = (const float*)d_in[0];
    const float* gate_w = (const float*)d_in[1];
    const float* fc1_w  = (const float*)d_in[2];
    const float* fc1_b  = (const float*)d_in[3];
    const float* fc2_w  = (const float*)d_in[4];
    const float* fc2_b  = (const float*)d_in[5];
    const float* sp1_w  = (const float*)d_in[6];
    const float* sp2_w  = (const float*)d_in[7];
    float* out = (float*)d_out;

    float *p_hsr = nullptr, *p_b1 = nullptr, *p_mid = nullptr, *p_b2 = nullptr;
    cudaGetSymbolAddress((void**)&p_hsr, g_hsr);
    cudaGetSymbolAddress((void**)&p_b1,  g_b1);
    cudaGetSymbolAddress((void**)&p_mid, g_mid);
    cudaGetSymbolAddress((void**)&p_b2,  g_b2);

    cudaFuncSetAttribute(mma_gemm<0>, cudaFuncAttributeMaxDynamicSharedMemorySize, SMEM_BYTES);
    cudaFuncSetAttribute(mma_gemm<1>, cudaFuncAttributeMaxDynamicSharedMemorySize, SMEM_BYTES);
    cudaFuncSetAttribute(mma_gemm<2>, cudaFuncAttributeMaxDynamicSharedMemorySize, SMEM_BYTES);

    zero_cnt_kernel<<<1, 32>>>();
    router_kernel<<<T, 256>>>(hs, gate_w);
    round_hs_kernel<<<(T * H / 4) / 256, 256>>>(hs);
    basis_kernel<0><<<(T * H) / 256, 256>>>(hs);

    // MLP experts (routing experts 0..3)
    mma_gemm<0><<<dim3(F / 128, 16, NM), 128, SMEM_BYTES>>>(
        p_hsr, 0, H, /*gather=*/1, /*eoff=*/0,
        fc1_w, (size_t)F * H,
        fc1_b, F,
        p_mid, (size_t)T * F, F,
        H);
    mma_gemm<2><<<dim3(H / 128, 16, NM), 128, SMEM_BYTES>>>(
        p_mid, (size_t)T * F, F, /*gather=*/0, /*eoff=*/0,
        fc2_w, (size_t)H * F,
        fc2_b, H,
        nullptr, 0, 0,
        F);

    // KAN experts (routing experts 4..7)
    mma_gemm<1><<<dim3(F2 / 128, 16, NM), 128, SMEM_BYTES>>>(
        p_b1, 0, HG, /*gather=*/1, /*eoff=*/NM,
        sp1_w, (size_t)F2 * HG,
        nullptr, 0,
        p_mid, (size_t)T * F, F2,
        HG);
    basis_kernel<1><<<dim3((T * F2) / 256, 1, NM), 256>>>(nullptr);
    mma_gemm<2><<<dim3(H / 128, 16, NM), 128, SMEM_BYTES>>>(
        p_b2, (size_t)T * FG2, FG2, /*gather=*/0, /*eoff=*/NM,
        sp2_w, (size_t)H * FG2,
        nullptr, 0,
        nullptr, 0, 0,
        FG2);

    combine_kernel<<<(T * H / 4) / 256, 256>>>(out);
}

// round 5
// speedup vs baseline: 5.2928x; 1.3651x over previous
#include <cuda_runtime.h>
#include <cuda_fp16.h>
#include <cstdint>
#include <math.h>

#define T 2048
#define H 1024
#define F 4096
#define E 8
#define NM 4
#define G 8
#define HG (H*G)      /* 8192  */
#define F2 (F/2)      /* 2048  */
#define FG2 (F2*G)    /* 16384 */

// ---------------- scratch (device globals; no allocation allowed) -------------
__device__ __half g_hsh[(size_t)T * H];              // fp16 hidden (GEMM A)
__device__ __half g_b1[(size_t)T * HG];              // fp16 rswaf(hidden)
__device__ __half g_midh[(size_t)NM * T * F];        // fp16 gelu(fc1)  (A of fc2)
__device__ float  g_k1[(size_t)NM * T * F2];         // fp32 k1 (basis input)
__device__ __half g_b2[(size_t)NM * T * FG2];        // fp16 rswaf(k1)
__device__ float  g_outslot[2][(size_t)T * H];       // per-(token,slot) outputs
__device__ int    g_tok[E][T];
__device__ float  g_wgt[E][T];
__device__ int    g_slot[E][T];
__device__ int    g_cnt[E];

// ---------------- helpers ------------------------------------------------------
__device__ __forceinline__ uint32_t pack_h2(float lo, float hi) {
    uint32_t r;
    asm("cvt.rn.f16x2.f32 %0, %2, %1;" : "=r"(r) : "f"(lo), "f"(hi));
    return r;
}
__device__ __forceinline__ void mma_f16(float* c, uint32_t a0, uint32_t a1,
                                        uint32_t a2, uint32_t a3,
                                        uint32_t b0, uint32_t b1) {
    asm volatile("mma.sync.aligned.m16n8k16.row.col.f32.f16.f16.f32 "
        "{%0,%1,%2,%3},{%4,%5,%6,%7},{%8,%9},{%0,%1,%2,%3};"
        : "+f"(c[0]), "+f"(c[1]), "+f"(c[2]), "+f"(c[3])
        : "r"(a0), "r"(a1), "r"(a2), "r"(a3), "r"(b0), "r"(b1));
}
__device__ __forceinline__ uint32_t smem_u32(const void* p) {
    uint32_t a;
    asm("{ .reg .u64 t; cvta.to.shared.u64 t, %1; cvt.u32.u64 %0, t; }" : "=r"(a) : "l"(p));
    return a;
}
#define CP_ASYNC16(dst, src) \
    asm volatile("cp.async.cg.shared.global [%0], [%1], 16;" :: "r"(dst), "l"(src))
#define CP_COMMIT()  asm volatile("cp.async.commit_group;" ::: "memory")
#define CP_WAIT0()   asm volatile("cp.async.wait_group 0;" ::: "memory")

// ---------------- small kernels ------------------------------------------------
__global__ void zero_cnt_kernel() {
    if (threadIdx.x < E) g_cnt[threadIdx.x] = 0;
}

__global__ void cvt_hs_kernel(const float* __restrict__ hs) {
    int i = blockIdx.x * blockDim.x + threadIdx.x;   // over T*H/4
    float4 v = ((const float4*)hs)[i];
    uint2 u = make_uint2(pack_h2(v.x, v.y), pack_h2(v.z, v.w));
    ((uint2*)g_hsh)[i] = u;
}

__global__ void router_kernel(const float* __restrict__ hs, const float* __restrict__ gw) {
    int t = blockIdx.x;
    int warp = threadIdx.x >> 5, lane = threadIdx.x & 31;
    const float* x = hs + (size_t)t * H;
    const float* g = gw + (size_t)warp * H;
    float s = 0.f;
    for (int k = lane; k < H; k += 32) s += x[k] * g[k];
    #pragma unroll
    for (int o = 16; o; o >>= 1) s += __shfl_xor_sync(0xFFFFFFFFu, s, o);
    __shared__ float logits[E];
    if (lane == 0) logits[warp] = s;
    __syncthreads();
    if (threadIdx.x == 0) {
        float l1 = -1e30f, l2 = -1e30f; int e1 = 0, e2 = 0;
        #pragma unroll
        for (int e = 0; e < E; e++) {
            float v = logits[e];
            if (v > l1) { l2 = l1; e2 = e1; l1 = v; e1 = e; }
            else if (v > l2) { l2 = v; e2 = e; }
        }
        float r  = expf(l2 - l1);
        float w1 = 1.0f / (1.0f + r);
        float w2 = r * w1;
        int p1 = atomicAdd(&g_cnt[e1], 1);
        g_tok[e1][p1] = t; g_wgt[e1][p1] = w1; g_slot[e1][p1] = 0;
        int p2 = atomicAdd(&g_cnt[e2], 1);
        g_tok[e2][p2] = t; g_wgt[e2][p2] = w2; g_slot[e2][p2] = 1;
    }
}

// rswaf basis; output fp16 (only ever a GEMM A operand)
template<int WHICH>
__global__ void basis_kernel(const float* __restrict__ src_param) {
    int idx = blockIdx.x * blockDim.x + threadIdx.x;
    const float* src; __half* dst;
    if (WHICH == 0) {
        src = src_param; dst = g_b1;
    } else {
        int z = blockIdx.z;
        int row = idx / F2;
        if (row >= g_cnt[NM + z]) return;
        src = g_k1 + (size_t)z * T * F2;
        dst = g_b2 + (size_t)z * T * FG2;
    }
    float x = src[idx];
    float r[8];
    #pragma unroll
    for (int i = 0; i < 8; i++) {
        float d = (x - (-1.2f + 0.2f * (float)i)) * 0.5f;
        float th = tanhf(d);
        r[i] = 1.0f - th * th;
    }
    uint4 u = make_uint4(pack_h2(r[0], r[1]), pack_h2(r[2], r[3]),
                         pack_h2(r[4], r[5]), pack_h2(r[6], r[7]));
    *(uint4*)(dst + (size_t)idx * 8) = u;
}

// ================= fp16 mma.sync GEMM v3 =======================================
// C[i,n] = sum_k A[i,k]*B[n,k]; A fp16 (pre-converted), B fp32 weights cvt inline.
// 128x128 tile, BK=64, 128 threads (4 warps 2x2, warp tile 64x64), 2 CTAs/SM.
// MODE 0: Ch = half(gelu(acc + bias)) -> g_midh   MODE 1: C = acc -> g_k1
// MODE 2: out = wgt * (acc [+bias]) -> g_outslot[slot][tok]
#define STAGE_BYTES 16384            /* 128 rows x 128 B (64 halves) */
#define SMEM_BYTES (4 * STAGE_BYTES) /* A0 A1 B0 B1 = 64KB */

template<int MODE>
__global__ __launch_bounds__(128, 2)
void mma_gemm(const __half* __restrict__ Abase, size_t Aslab, int lda, int gather, int eoff,
              const float* __restrict__ Bbase, size_t Bslab,
              const float* __restrict__ biasbase, int biasslab,
              float* __restrict__ Cbase, __half* __restrict__ Chbase,
              size_t Cslab, int ldc, int K) {
    int z = blockIdx.z, expert = eoff + z;
    int cnt = g_cnt[expert];
    int by = blockIdx.y, bx = blockIdx.x;
    if (by * 128 >= cnt) return;

    extern __shared__ __align__(16) char smem[];
    uint32_t sb = smem_u32(smem);
    char* sA[2] = { smem,                   smem + STAGE_BYTES };
    char* sB[2] = { smem + 2 * STAGE_BYTES, smem + 3 * STAGE_BYTES };

    const __half* A = Abase + (size_t)z * Aslab;
    const float*  B = Bbase + (size_t)z * Bslab;

    int tid = threadIdx.x;
    int c  = tid & 7;        // 16B dest group (8 halves)
    int r0 = tid >> 3;       // 0..15; rows r0 + 16j
    uint32_t a_off[8], b_off[8], st_byte[8];
    #pragma unroll
    for (int j = 0; j < 8; j++) {
        int row = r0 + 16 * j;
        int arow;
        if (gather) {
            int gi = by * 128 + row;
            if (gi >= cnt) gi = cnt - 1;
            arow = g_tok[expert][gi];
        } else {
            arow = by * 128 + row;
        }
        a_off[j]  = (uint32_t)arow * (uint32_t)lda * 2u + c * 16u;
        b_off[j]  = (uint32_t)(bx * 128 + row) * (uint32_t)K * 4u + c * 32u;
        st_byte[j] = row * 128 + ((c ^ (row & 7)) << 4);
    }

    int wid = tid >> 5, lane = tid & 31;
    int wm = wid >> 1, wn = wid & 1;
    int gp = lane >> 2, tig = lane & 3;

    float acc[4][8][4];
    #pragma unroll
    for (int mt = 0; mt < 4; mt++)
        #pragma unroll
        for (int nt = 0; nt < 8; nt++)
            #pragma unroll
            for (int q = 0; q < 4; q++) acc[mt][nt][q] = 0.f;

    int nch = K >> 6;   // BK = 64

    // ---- prologue: stage chunk 0 ----
    #pragma unroll
    for (int j = 0; j < 8; j++)
        CP_ASYNC16(sb + st_byte[j], (const char*)A + a_off[j]);
    CP_COMMIT();
    #pragma unroll
    for (int j = 0; j < 8; j++) {
        float4 v0 = *(const float4*)((const char*)B + b_off[j]);
        float4 v1 = *(const float4*)((const char*)B + b_off[j] + 16);
        uint4 u = make_uint4(pack_h2(v0.x, v0.y), pack_h2(v0.z, v0.w),
                             pack_h2(v1.x, v1.y), pack_h2(v1.z, v1.w));
        *(uint4*)(sB[0] + st_byte[j]) = u;
    }
    CP_WAIT0();
    __syncthreads();

    for (int i = 0; i < nch; i++) {
        int s = i & 1;
        bool pre = (i + 1 < nch);
        uint32_t ka = (uint32_t)(i + 1) * 128u;   // A byte stride per chunk
        uint32_t kb = (uint32_t)(i + 1) * 256u;   // B byte stride per chunk
        if (pre) {
            uint32_t dst_a = sb + (s ^ 1) * STAGE_BYTES;
            #pragma unroll
            for (int j = 0; j < 8; j++)
                CP_ASYNC16(dst_a + st_byte[j], (const char*)A + a_off[j] + ka);
            CP_COMMIT();
        }
        const char* As = sA[s];
        const char* Bs = sB[s];

        float4 bb[4][2];
        if (pre) {
            #pragma unroll
            for (int j = 0; j < 4; j++) {
                bb[j][0] = *(const float4*)((const char*)B + b_off[j] + kb);
                bb[j][1] = *(const float4*)((const char*)B + b_off[j] + kb + 16);
            }
        }

        #pragma unroll
        for (int ks = 0; ks < 4; ks++) {
            if (ks == 2 && pre) {
                char* Bd = sB[s ^ 1];
                #pragma unroll
                for (int j = 0; j < 4; j++) {
                    uint4 u = make_uint4(pack_h2(bb[j][0].x, bb[j][0].y), pack_h2(bb[j][0].z, bb[j][0].w),
                                         pack_h2(bb[j][1].x, bb[j][1].y), pack_h2(bb[j][1].z, bb[j][1].w));
                    *(uint4*)(Bd + st_byte[j]) = u;
                }
                #pragma unroll
                for (int j = 4; j < 8; j++) {
                    bb[j - 4][0] = *(const float4*)((const char*)B + b_off[j] + kb);
                    bb[j - 4][1] = *(const float4*)((const char*)B + b_off[j] + kb + 16);
                }
            }
            int o0 = (((2 * ks)     ^ gp) << 4) + 4 * tig;
            int o1 = (((2 * ks + 1) ^ gp) << 4) + 4 * tig;
            uint32_t bf[8][2];
            #pragma unroll
            for (int nt = 0; nt < 8; nt++) {
                int rb = (wn * 64 + nt * 8 + gp) * 128;
                bf[nt][0] = *(const uint32_t*)(Bs + rb + o0);
                bf[nt][1] = *(const uint32_t*)(Bs + rb + o1);
            }
            #pragma unroll
            for (int mt = 0; mt < 4; mt++) {
                int ra = (wm * 64 + mt * 16 + gp) * 128;
                uint32_t a0 = *(const uint32_t*)(As + ra + o0);
                uint32_t a1 = *(const uint32_t*)(As + ra + 1024 + o0);
                uint32_t a2 = *(const uint32_t*)(As + ra + o1);
                uint32_t a3 = *(const uint32_t*)(As + ra + 1024 + o1);
                #pragma unroll
                for (int nt = 0; nt < 8; nt++)
                    mma_f16(acc[mt][nt], a0, a1, a2, a3, bf[nt][0], bf[nt][1]);
            }
        }

        if (pre) {
            char* Bd = sB[s ^ 1];
            #pragma unroll
            for (int j = 4; j < 8; j++) {
                uint4 u = make_uint4(pack_h2(bb[j-4][0].x, bb[j-4][0].y), pack_h2(bb[j-4][0].z, bb[j-4][0].w),
                                     pack_h2(bb[j-4][1].x, bb[j-4][1].y), pack_h2(bb[j-4][1].z, bb[j-4][1].w));
                *(uint4*)(Bd + st_byte[j]) = u;
            }
            CP_WAIT0();
        }
        __syncthreads();
    }

    // ---- epilogue ----
    const float* bias = nullptr;
    if (MODE == 0) bias = biasbase + (size_t)z * biasslab;
    if (MODE == 2 && biasbase) bias = biasbase + (size_t)z * biasslab;

    #pragma unroll
    for (int mt = 0; mt < 4; mt++) {
        #pragma unroll
        for (int half = 0; half < 2; half++) {
            int row = by * 128 + wm * 64 + mt * 16 + gp + half * 8;
            if (row >= cnt) continue;
            float* dst = nullptr; __half* dsth = nullptr;
            float wv = 1.f;
            if (MODE == 0) {
                dsth = Chbase + (size_t)z * Cslab + (size_t)row * ldc;
            } else if (MODE == 1) {
                dst = Cbase + (size_t)z * Cslab + (size_t)row * ldc;
            } else {
                int   t  = g_tok[expert][row];
                int   sl = g_slot[expert][row];
                wv = g_wgt[expert][row];
                dst = &g_outslot[sl][(size_t)t * H];
            }
            #pragma unroll
            for (int nt = 0; nt < 8; nt++) {
                int col = bx * 128 + wn * 64 + nt * 8 + 2 * tig;
                float v0 = acc[mt][nt][half * 2];
                float v1 = acc[mt][nt][half * 2 + 1];
                if (MODE == 0) {
                    v0 += bias[col];     v1 += bias[col + 1];
                    v0 = 0.5f * v0 * (1.0f + erff(v0 * 0.70710678118654752f));
                    v1 = 0.5f * v1 * (1.0f + erff(v1 * 0.70710678118654752f));
                    *(uint32_t*)(dsth + col) = pack_h2(v0, v1);
                } else if (MODE == 2) {
                    if (bias) { v0 += bias[col]; v1 += bias[col + 1]; }
                    *(float2*)(dst + col) = make_float2(v0 * wv, v1 * wv);
                } else {
                    *(float2*)(dst + col) = make_float2(v0, v1);
                }
            }
        }
    }
}

__global__ void combine_kernel(float* __restrict__ out) {
    int i = blockIdx.x * blockDim.x + threadIdx.x;
    float4 a = ((const float4*)g_outslot[0])[i];
    float4 b = ((const float4*)g_outslot[1])[i];
    ((float4*)out)[i] = make_float4(a.x + b.x, a.y + b.y, a.z + b.z, a.w + b.w);
}

// ---------------- launch --------------------------------------------------------
extern "C" void kernel_launch(void* const* d_in, const int* in_sizes, int n_in,
                              void* d_out, int out_size) {
    const float* hs     = (const float*)d_in[0];
    const float* gate_w = (const float*)d_in[1];
    const float* fc1_w  = (const float*)d_in[2];
    const float* fc1_b  = (const float*)d_in[3];
    const float* fc2_w  = (const float*)d_in[4];
    const float* fc2_b  = (const float*)d_in[5];
    const float* sp1_w  = (const float*)d_in[6];
    const float* sp2_w  = (const float*)d_in[7];
    float* out = (float*)d_out;

    __half *p_hsh = nullptr, *p_b1 = nullptr, *p_midh = nullptr, *p_b2 = nullptr;
    float  *p_k1 = nullptr;
    cudaGetSymbolAddress((void**)&p_hsh,  g_hsh);
    cudaGetSymbolAddress((void**)&p_b1,   g_b1);
    cudaGetSymbolAddress((void**)&p_midh, g_midh);
    cudaGetSymbolAddress((void**)&p_k1,   g_k1);
    cudaGetSymbolAddress((void**)&p_b2,   g_b2);

    cudaFuncSetAttribute(mma_gemm<0>, cudaFuncAttributeMaxDynamicSharedMemorySize, SMEM_BYTES);
    cudaFuncSetAttribute(mma_gemm<1>, cudaFuncAttributeMaxDynamicSharedMemorySize, SMEM_BYTES);
    cudaFuncSetAttribute(mma_gemm<2>, cudaFuncAttributeMaxDynamicSharedMemorySize, SMEM_BYTES);

    zero_cnt_kernel<<<1, 32>>>();
    router_kernel<<<T, 256>>>(hs, gate_w);
    cvt_hs_kernel<<<(T * H / 4) / 256, 256>>>(hs);
    basis_kernel<0><<<(T * H) / 256, 256>>>(hs);

    // MLP experts (routing experts 0..3)
    mma_gemm<0><<<dim3(F / 128, 16, NM), 128, SMEM_BYTES>>>(
        p_hsh, 0, H, /*gather=*/1, /*eoff=*/0,
        fc1_w, (size_t)F * H,
        fc1_b, F,
        nullptr, p_midh, (size_t)T * F, F,
        H);
    mma_gemm<2><<<dim3(H / 128, 16, NM), 128, SMEM_BYTES>>>(
        p_midh, (size_t)T * F, F, /*gather=*/0, /*eoff=*/0,
        fc2_w, (size_t)H * F,
        fc2_b, H,
        nullptr, nullptr, 0, 0,
        F);

    // KAN experts (routing experts 4..7)
    mma_gemm<1><<<dim3(F2 / 128, 16, NM), 128, SMEM_BYTES>>>(
        p_b1, 0, HG, /*gather=*/1, /*eoff=*/NM,
        sp1_w, (size_t)F2 * HG,
        nullptr, 0,
        p_k1, nullptr, (size_t)T * F2, F2,
        HG);
    basis_kernel<1><<<dim3((T * F2) / 256, 1, NM), 256>>>(nullptr);
    mma_gemm<2><<<dim3(H / 128, 16, NM), 128, SMEM_BYTES>>>(
        p_b2, (size_t)T * FG2, FG2, /*gather=*/0, /*eoff=*/NM,
        sp2_w, (size_t)H * FG2,
        nullptr, 0,
        nullptr, nullptr, 0, 0,
        FG2);

    combine_kernel<<<(T * H / 4) / 256, 256>>>(out);
}

// round 6
// speedup vs baseline: 6.8028x; 1.2853x over previous
#include <cuda_runtime.h>
#include <cuda_fp16.h>
#include <cstdint>
#include <math.h>

#define T 2048
#define H 1024
#define F 4096
#define E 8
#define NM 4
#define G 8
#define HG (H*G)      /* 8192  */
#define F2 (F/2)      /* 2048  */
#define FG2 (F2*G)    /* 16384 */

// ---------------- scratch (device globals; no allocation allowed) -------------
__device__ __half g_hsh[(size_t)T * H];              // fp16 hidden (GEMM A)
__device__ __half g_b1[(size_t)T * HG];              // fp16 rswaf(hidden)
__device__ __half g_midh[(size_t)NM * T * F];        // fp16 gelu(fc1)  (A of fc2)
__device__ float  g_k1[(size_t)NM * T * F2];         // fp32 k1 (basis input)
__device__ __half g_b2[(size_t)NM * T * FG2];        // fp16 rswaf(k1)
__device__ float  g_outslot[2][(size_t)T * H];       // per-(token,slot) outputs
__device__ int    g_tok[E][T];
__device__ float  g_wgt[E][T];
__device__ int    g_slot[E][T];
__device__ int    g_cnt[E];

// ---------------- helpers ------------------------------------------------------
__device__ __forceinline__ uint32_t pack_h2(float lo, float hi) {
    uint32_t r;
    asm("cvt.rn.f16x2.f32 %0, %2, %1;" : "=r"(r) : "f"(lo), "f"(hi));
    return r;
}
__device__ __forceinline__ void mma_f16(float* c, uint32_t a0, uint32_t a1,
                                        uint32_t a2, uint32_t a3,
                                        uint32_t b0, uint32_t b1) {
    asm volatile("mma.sync.aligned.m16n8k16.row.col.f32.f16.f16.f32 "
        "{%0,%1,%2,%3},{%4,%5,%6,%7},{%8,%9},{%0,%1,%2,%3};"
        : "+f"(c[0]), "+f"(c[1]), "+f"(c[2]), "+f"(c[3])
        : "r"(a0), "r"(a1), "r"(a2), "r"(a3), "r"(b0), "r"(b1));
}
__device__ __forceinline__ uint32_t smem_u32(const void* p) {
    uint32_t a;
    asm("{ .reg .u64 t; cvta.to.shared.u64 t, %1; cvt.u32.u64 %0, t; }" : "=r"(a) : "l"(p));
    return a;
}
#define LDSM_X4(r0, r1, r2, r3, addr) \
    asm volatile("ldmatrix.sync.aligned.m8n8.x4.shared.b16 {%0,%1,%2,%3}, [%4];" \
        : "=r"(r0), "=r"(r1), "=r"(r2), "=r"(r3) : "r"(addr))
#define CP_ASYNC16(dst, src) \
    asm volatile("cp.async.cg.shared.global [%0], [%1], 16;" :: "r"(dst), "l"(src))
#define CP_COMMIT()  asm volatile("cp.async.commit_group;" ::: "memory")
#define CP_WAIT0()   asm volatile("cp.async.wait_group 0;" ::: "memory")

// ---------------- small kernels ------------------------------------------------
__global__ void zero_cnt_kernel() {
    if (threadIdx.x < E) g_cnt[threadIdx.x] = 0;
}

__global__ void cvt_hs_kernel(const float* __restrict__ hs) {
    int i = blockIdx.x * blockDim.x + threadIdx.x;   // over T*H/4
    float4 v = ((const float4*)hs)[i];
    uint2 u = make_uint2(pack_h2(v.x, v.y), pack_h2(v.z, v.w));
    ((uint2*)g_hsh)[i] = u;
}

__global__ void router_kernel(const float* __restrict__ hs, const float* __restrict__ gw) {
    int t = blockIdx.x;
    int warp = threadIdx.x >> 5, lane = threadIdx.x & 31;
    const float* x = hs + (size_t)t * H;
    const float* g = gw + (size_t)warp * H;
    float s = 0.f;
    for (int k = lane; k < H; k += 32) s += x[k] * g[k];
    #pragma unroll
    for (int o = 16; o; o >>= 1) s += __shfl_xor_sync(0xFFFFFFFFu, s, o);
    __shared__ float logits[E];
    if (lane == 0) logits[warp] = s;
    __syncthreads();
    if (threadIdx.x == 0) {
        float l1 = -1e30f, l2 = -1e30f; int e1 = 0, e2 = 0;
        #pragma unroll
        for (int e = 0; e < E; e++) {
            float v = logits[e];
            if (v > l1) { l2 = l1; e2 = e1; l1 = v; e1 = e; }
            else if (v > l2) { l2 = v; e2 = e; }
        }
        float r  = expf(l2 - l1);
        float w1 = 1.0f / (1.0f + r);
        float w2 = r * w1;
        int p1 = atomicAdd(&g_cnt[e1], 1);
        g_tok[e1][p1] = t; g_wgt[e1][p1] = w1; g_slot[e1][p1] = 0;
        int p2 = atomicAdd(&g_cnt[e2], 1);
        g_tok[e2][p2] = t; g_wgt[e2][p2] = w2; g_slot[e2][p2] = 1;
    }
}

// rswaf basis; output fp16 (only ever a GEMM A operand)
template<int WHICH>
__global__ void basis_kernel(const float* __restrict__ src_param) {
    int idx = blockIdx.x * blockDim.x + threadIdx.x;
    const float* src; __half* dst;
    if (WHICH == 0) {
        src = src_param; dst = g_b1;
    } else {
        int z = blockIdx.z;
        int row = idx / F2;
        if (row >= g_cnt[NM + z]) return;
        src = g_k1 + (size_t)z * T * F2;
        dst = g_b2 + (size_t)z * T * FG2;
    }
    float x = src[idx];
    float r[8];
    #pragma unroll
    for (int i = 0; i < 8; i++) {
        float d = (x - (-1.2f + 0.2f * (float)i)) * 0.5f;
        float th = tanhf(d);
        r[i] = 1.0f - th * th;
    }
    uint4 u = make_uint4(pack_h2(r[0], r[1]), pack_h2(r[2], r[3]),
                         pack_h2(r[4], r[5]), pack_h2(r[6], r[7]));
    *(uint4*)(dst + (size_t)idx * 8) = u;
}

// ================= fp16 mma.sync GEMM v4 (ldmatrix) ============================
// 128x128 tile, BK=64, 128 threads (4 warps 2x2, warp tile 64x64), 2 CTAs/SM.
// A fp16 pre-converted -> cp.async; B fp32 weights -> LDG+cvt+STS.
// Fragment loads via ldmatrix.m8n8.x4.
#define STAGE_BYTES 16384            /* 128 rows x 128 B (64 halves) */
#define SMEM_BYTES (4 * STAGE_BYTES) /* A0 A1 B0 B1 = 64KB */

template<int MODE>
__global__ __launch_bounds__(128, 2)
void mma_gemm(const __half* __restrict__ Abase, size_t Aslab, int lda, int gather, int eoff,
              const float* __restrict__ Bbase, size_t Bslab,
              const float* __restrict__ biasbase, int biasslab,
              float* __restrict__ Cbase, __half* __restrict__ Chbase,
              size_t Cslab, int ldc, int K) {
    int z = blockIdx.z, expert = eoff + z;
    int cnt = g_cnt[expert];
    int by = blockIdx.y, bx = blockIdx.x;
    if (by * 128 >= cnt) return;

    extern __shared__ __align__(16) char smem[];
    uint32_t sb = smem_u32(smem);
    char* sB[2] = { smem + 2 * STAGE_BYTES, smem + 3 * STAGE_BYTES };

    const __half* A = Abase + (size_t)z * Aslab;
    const float*  B = Bbase + (size_t)z * Bslab;

    int tid = threadIdx.x;
    int c  = tid & 7;        // 16B dest group (8 halves)
    int r0 = tid >> 3;       // 0..15; rows r0 + 16j
    uint32_t a_off[8], b_off[8], st_byte[8];
    #pragma unroll
    for (int j = 0; j < 8; j++) {
        int row = r0 + 16 * j;
        int arow;
        if (gather) {
            int gi = by * 128 + row;
            if (gi >= cnt) gi = cnt - 1;
            arow = g_tok[expert][gi];
        } else {
            arow = by * 128 + row;
        }
        a_off[j]  = (uint32_t)arow * (uint32_t)lda * 2u + c * 16u;
        b_off[j]  = (uint32_t)(bx * 128 + row) * (uint32_t)K * 4u + c * 32u;
        st_byte[j] = row * 128 + ((c ^ (row & 7)) << 4);
    }

    int wid = tid >> 5, lane = tid & 31;
    int wm = wid >> 1, wn = wid & 1;
    int gp = lane >> 2, tig = lane & 3;
    int r7 = lane & 7;

    // ldmatrix lane address components
    uint32_t baseA = (uint32_t)(wm * 64 + (lane & 15)) * 128u;
    uint32_t baseB = (uint32_t)(wn * 64 + (lane & 7) + ((lane >> 4) << 3)) * 128u;
    uint32_t hiA = (lane >> 4) & 1;
    uint32_t hiB = (lane >> 3) & 1;
    uint32_t xa[4], xb[4];
    #pragma unroll
    for (int ks = 0; ks < 4; ks++) {
        xa[ks] = (uint32_t)(((2 * ks + hiA) ^ r7) << 4);
        xb[ks] = (uint32_t)(((2 * ks + hiB) ^ r7) << 4);
    }

    float acc[4][8][4];
    #pragma unroll
    for (int mt = 0; mt < 4; mt++)
        #pragma unroll
        for (int nt = 0; nt < 8; nt++)
            #pragma unroll
            for (int q = 0; q < 4; q++) acc[mt][nt][q] = 0.f;

    int nch = K >> 6;   // BK = 64

    // ---- prologue: stage chunk 0 ----
    #pragma unroll
    for (int j = 0; j < 8; j++)
        CP_ASYNC16(sb + st_byte[j], (const char*)A + a_off[j]);
    CP_COMMIT();
    #pragma unroll
    for (int j = 0; j < 8; j++) {
        float4 v0 = *(const float4*)((const char*)B + b_off[j]);
        float4 v1 = *(const float4*)((const char*)B + b_off[j] + 16);
        uint4 u = make_uint4(pack_h2(v0.x, v0.y), pack_h2(v0.z, v0.w),
                             pack_h2(v1.x, v1.y), pack_h2(v1.z, v1.w));
        *(uint4*)(sB[0] + st_byte[j]) = u;
    }
    CP_WAIT0();
    __syncthreads();

    for (int i = 0; i < nch; i++) {
        int s = i & 1;
        bool pre = (i + 1 < nch);
        uint32_t ka = (uint32_t)(i + 1) * 128u;   // A byte stride per chunk
        uint32_t kb = (uint32_t)(i + 1) * 256u;   // B byte stride per chunk
        if (pre) {
            uint32_t dst_a = sb + (s ^ 1) * STAGE_BYTES;
            #pragma unroll
            for (int j = 0; j < 8; j++)
                CP_ASYNC16(dst_a + st_byte[j], (const char*)A + a_off[j] + ka);
            CP_COMMIT();
        }
        uint32_t aA = sb + s * STAGE_BYTES + baseA;
        uint32_t aB = sb + (2 + s) * STAGE_BYTES + baseB;

        float4 bb[4][2];
        if (pre) {
            #pragma unroll
            for (int j = 0; j < 4; j++) {
                bb[j][0] = *(const float4*)((const char*)B + b_off[j] + kb);
                bb[j][1] = *(const float4*)((const char*)B + b_off[j] + kb + 16);
            }
        }

        #pragma unroll
        for (int ks = 0; ks < 4; ks++) {
            if (ks == 2 && pre) {
                char* Bd = sB[s ^ 1];
                #pragma unroll
                for (int j = 0; j < 4; j++) {
                    uint4 u = make_uint4(pack_h2(bb[j][0].x, bb[j][0].y), pack_h2(bb[j][0].z, bb[j][0].w),
                                         pack_h2(bb[j][1].x, bb[j][1].y), pack_h2(bb[j][1].z, bb[j][1].w));
                    *(uint4*)(Bd + st_byte[j]) = u;
                }
                #pragma unroll
                for (int j = 4; j < 8; j++) {
                    bb[j - 4][0] = *(const float4*)((const char*)B + b_off[j] + kb);
                    bb[j - 4][1] = *(const float4*)((const char*)B + b_off[j] + kb + 16);
                }
            }
            // B fragments: 4 ldmatrix.x4, each covers an nt pair
            uint32_t bf[8][2];
            #pragma unroll
            for (int p = 0; p < 4; p++)
                LDSM_X4(bf[2*p][0], bf[2*p][1], bf[2*p+1][0], bf[2*p+1][1],
                        aB + p * 2048u + xb[ks]);
            #pragma unroll
            for (int mt = 0; mt < 4; mt++) {
                uint32_t a0, a1, a2, a3;
                LDSM_X4(a0, a1, a2, a3, aA + mt * 2048u + xa[ks]);
                #pragma unroll
                for (int nt = 0; nt < 8; nt++)
                    mma_f16(acc[mt][nt], a0, a1, a2, a3, bf[nt][0], bf[nt][1]);
            }
        }

        if (pre) {
            char* Bd = sB[s ^ 1];
            #pragma unroll
            for (int j = 4; j < 8; j++) {
                uint4 u = make_uint4(pack_h2(bb[j-4][0].x, bb[j-4][0].y), pack_h2(bb[j-4][0].z, bb[j-4][0].w),
                                     pack_h2(bb[j-4][1].x, bb[j-4][1].y), pack_h2(bb[j-4][1].z, bb[j-4][1].w));
                *(uint4*)(Bd + st_byte[j]) = u;
            }
            CP_WAIT0();
        }
        __syncthreads();
    }

    // ---- epilogue ----
    const float* bias = nullptr;
    if (MODE == 0) bias = biasbase + (size_t)z * biasslab;
    if (MODE == 2 && biasbase) bias = biasbase + (size_t)z * biasslab;

    #pragma unroll
    for (int mt = 0; mt < 4; mt++) {
        #pragma unroll
        for (int half = 0; half < 2; half++) {
            int row = by * 128 + wm * 64 + mt * 16 + gp + half * 8;
            if (row >= cnt) continue;
            float* dst = nullptr; __half* dsth = nullptr;
            float wv = 1.f;
            if (MODE == 0) {
                dsth = Chbase + (size_t)z * Cslab + (size_t)row * ldc;
            } else if (MODE == 1) {
                dst = Cbase + (size_t)z * Cslab + (size_t)row * ldc;
            } else {
                int   t  = g_tok[expert][row];
                int   sl = g_slot[expert][row];
                wv = g_wgt[expert][row];
                dst = &g_outslot[sl][(size_t)t * H];
            }
            #pragma unroll
            for (int nt = 0; nt < 8; nt++) {
                int col = bx * 128 + wn * 64 + nt * 8 + 2 * tig;
                float v0 = acc[mt][nt][half * 2];
                float v1 = acc[mt][nt][half * 2 + 1];
                if (MODE == 0) {
                    v0 += bias[col];     v1 += bias[col + 1];
                    v0 = 0.5f * v0 * (1.0f + erff(v0 * 0.70710678118654752f));
                    v1 = 0.5f * v1 * (1.0f + erff(v1 * 0.70710678118654752f));
                    *(uint32_t*)(dsth + col) = pack_h2(v0, v1);
                } else if (MODE == 2) {
                    if (bias) { v0 += bias[col]; v1 += bias[col + 1]; }
                    *(float2*)(dst + col) = make_float2(v0 * wv, v1 * wv);
                } else {
                    *(float2*)(dst + col) = make_float2(v0, v1);
                }
            }
        }
    }
}

__global__ void combine_kernel(float* __restrict__ out) {
    int i = blockIdx.x * blockDim.x + threadIdx.x;
    float4 a = ((const float4*)g_outslot[0])[i];
    float4 b = ((const float4*)g_outslot[1])[i];
    ((float4*)out)[i] = make_float4(a.x + b.x, a.y + b.y, a.z + b.z, a.w + b.w);
}

// ---------------- launch --------------------------------------------------------
extern "C" void kernel_launch(void* const* d_in, const int* in_sizes, int n_in,
                              void* d_out, int out_size) {
    const float* hs     = (const float*)d_in[0];
    const float* gate_w = (const float*)d_in[1];
    const float* fc1_w  = (const float*)d_in[2];
    const float* fc1_b  = (const float*)d_in[3];
    const float* fc2_w  = (const float*)d_in[4];
    const float* fc2_b  = (const float*)d_in[5];
    const float* sp1_w  = (const float*)d_in[6];
    const float* sp2_w  = (const float*)d_in[7];
    float* out = (float*)d_out;

    __half *p_hsh = nullptr, *p_b1 = nullptr, *p_midh = nullptr, *p_b2 = nullptr;
    float  *p_k1 = nullptr;
    cudaGetSymbolAddress((void**)&p_hsh,  g_hsh);
    cudaGetSymbolAddress((void**)&p_b1,   g_b1);
    cudaGetSymbolAddress((void**)&p_midh, g_midh);
    cudaGetSymbolAddress((void**)&p_k1,   g_k1);
    cudaGetSymbolAddress((void**)&p_b2,   g_b2);

    cudaFuncSetAttribute(mma_gemm<0>, cudaFuncAttributeMaxDynamicSharedMemorySize, SMEM_BYTES);
    cudaFuncSetAttribute(mma_gemm<1>, cudaFuncAttributeMaxDynamicSharedMemorySize, SMEM_BYTES);
    cudaFuncSetAttribute(mma_gemm<2>, cudaFuncAttributeMaxDynamicSharedMemorySize, SMEM_BYTES);

    zero_cnt_kernel<<<1, 32>>>();
    router_kernel<<<T, 256>>>(hs, gate_w);
    cvt_hs_kernel<<<(T * H / 4) / 256, 256>>>(hs);
    basis_kernel<0><<<(T * H) / 256, 256>>>(hs);

    // MLP experts (routing experts 0..3)
    mma_gemm<0><<<dim3(F / 128, 16, NM), 128, SMEM_BYTES>>>(
        p_hsh, 0, H, /*gather=*/1, /*eoff=*/0,
        fc1_w, (size_t)F * H,
        fc1_b, F,
        nullptr, p_midh, (size_t)T * F, F,
        H);
    mma_gemm<2><<<dim3(H / 128, 16, NM), 128, SMEM_BYTES>>>(
        p_midh, (size_t)T * F, F, /*gather=*/0, /*eoff=*/0,
        fc2_w, (size_t)H * F,
        fc2_b, H,
        nullptr, nullptr, 0, 0,
        F);

    // KAN experts (routing experts 4..7)
    mma_gemm<1><<<dim3(F2 / 128, 16, NM), 128, SMEM_BYTES>>>(
        p_b1, 0, HG, /*gather=*/1, /*eoff=*/NM,
        sp1_w, (size_t)F2 * HG,
        nullptr, 0,
        p_k1, nullptr, (size_t)T * F2, F2,
        HG);
    basis_kernel<1><<<dim3((T * F2) / 256, 1, NM), 256>>>(nullptr);
    mma_gemm<2><<<dim3(H / 128, 16, NM), 128, SMEM_BYTES>>>(
        p_b2, (size_t)T * FG2, FG2, /*gather=*/0, /*eoff=*/NM,
        sp2_w, (size_t)H * FG2,
        nullptr, 0,
        nullptr, nullptr, 0, 0,
        FG2);

    combine_kernel<<<(T * H / 4) / 256, 256>>>(out);
}